// round 16
// baseline (speedup 1.0000x reference)
#include <cuda_runtime.h>
#include <cuda_bf16.h>
#include <math.h>

// Fixed shapes
#define B_ 32
#define C_ 6
#define T_ 64
#define K_ 8
#define N_ 128
#define NSEG 1016
#define NSEGP 1024
#define NCL 2048
#define NCLP2 1024             // candidate pairs
#define EPS_ 1e-6f
#define THRESH_ 0.5f
#define PAD_ 1e9f

#define THREADS 256
#define WARPS 8                // each warp = independent point group
#define M 4                    // points per warp
#define PTS_BLK (WARPS * M)    // 32
#define HALVES (T_ / PTS_BLK)  // 2
// grid = B*C*HALVES = 384

typedef unsigned long long u64;

__device__ float    g_scratch[B_ * C_ * 2];   // zero-init (.bss)
__device__ unsigned g_tick[B_ * C_];          // zero-init, reset after use

__device__ __forceinline__ u64 F2ADD(u64 a, u64 b) {
    u64 d; asm("add.rn.f32x2 %0,%1,%2;" : "=l"(d) : "l"(a), "l"(b)); return d;
}
__device__ __forceinline__ u64 F2SUB(u64 a, u64 b) {
    u64 d; asm("sub.rn.f32x2 %0,%1,%2;" : "=l"(d) : "l"(a), "l"(b)); return d;
}
__device__ __forceinline__ u64 F2MUL(u64 a, u64 b) {
    u64 d; asm("mul.rn.f32x2 %0,%1,%2;" : "=l"(d) : "l"(a), "l"(b)); return d;
}
__device__ __forceinline__ u64 F2FMA(u64 a, u64 b, u64 c) {
    u64 d; asm("fma.rn.f32x2 %0,%1,%2,%3;" : "=l"(d) : "l"(a), "l"(b), "l"(c)); return d;
}
__device__ __forceinline__ u64 F2PK(float lo, float hi) {
    u64 d; asm("mov.b64 %0,{%1,%2};" : "=l"(d) : "f"(lo), "f"(hi)); return d;
}
__device__ __forceinline__ void F2UP(u64 a, float& lo, float& hi) {
    asm("mov.b64 {%0,%1},%2;" : "=f"(lo), "=f"(hi) : "l"(a));
}
__device__ __forceinline__ float frcp(float x) {
    float r; asm("rcp.approx.f32 %0,%1;" : "=f"(r) : "f"(x)); return r;
}

__global__ __launch_bounds__(THREADS, 3)
void offroad_kernel(const float* __restrict__ points,
                    const float* __restrict__ road_boundary,
                    const float* __restrict__ centerlines,
                    float* __restrict__ out) {
    __shared__ float4 sA[NSEGP];     // (-ax,-ax,-ay,-ay)
    __shared__ float4 sD[NSEGP];     // (-dx,-dx,-dy,-dy)
    __shared__ float4 sCl[NCLP2];    // (-qx0,-qx1,-qy0,-qy1) per cand pair
    __shared__ float2 sClh[NCLP2];   // (h0,h1) = 0.5*|q|^2 per pair
    __shared__ float  sVal[WARPS];

    const int bid = blockIdx.x;
    const int half = bid & 1;
    const int c = (bid >> 1) % C_;
    const int b = bid / (2 * C_);
    const int idx = b * C_ + c;
    const int tid = threadIdx.x;

    const int w = tid >> 5;     // warp = point group (0..7)
    const int l = tid & 31;

    // ---- issue the points load FIRST (latency overlapped with prologue) ----
    float px[M], py[M];
    {
        const float2* pp = (const float2*)points +
            ((size_t)idx) * T_ + half * PTS_BLK + w * M;
        #pragma unroll
        for (int j = 0; j < M; j++) { float2 p = pp[j]; px[j] = p.x; py[j] = p.y; }
    }

    // ---- prologue: batch ALL global loads, then all stores ----
    {
        const float2* rb = (const float2*)road_boundary + (size_t)b * K_ * N_;
        const float4* cl4 = (const float4*)(centerlines + (size_t)b * NCL * 2);
        float2 aR[4], eR[4];
        float4 vR[4];
        #pragma unroll
        for (int i = 0; i < 4; i++) {
            int s = tid + i * THREADS;
            int ss = (s < NSEG) ? s : 0;
            int k = ss / (N_ - 1);
            int j = ss - k * (N_ - 1);
            aR[i] = rb[k * N_ + j];
            eR[i] = rb[k * N_ + j + 1];
        }
        #pragma unroll
        for (int i = 0; i < 4; i++) vR[i] = cl4[tid + i * THREADS];

        #pragma unroll
        for (int i = 0; i < 4; i++) {
            int s = tid + i * THREADS;
            float nax, nay, ndx, ndy;
            if (s < NSEG) {
                nax = -aR[i].x; nay = -aR[i].y;
                ndx = aR[i].x - eR[i].x; ndy = aR[i].y - eR[i].y;
            } else {
                nax = -PAD_; nay = -PAD_;   // a = (PAD, PAD), d = (1,0): inert
                ndx = -1.0f; ndy = 0.0f;
            }
            sA[s] = make_float4(nax, nax, nay, nay);
            sD[s] = make_float4(ndx, ndx, ndy, ndy);
        }
        #pragma unroll
        for (int i = 0; i < 4; i++) {
            int pi = tid + i * THREADS;
            float4 v = vR[i];   // (q0x,q0y,q1x,q1y)
            sCl[pi] = make_float4(-v.x, -v.z, -v.y, -v.w);
            sClh[pi] = make_float2(0.5f * fmaf(v.x, v.x, v.y * v.y),
                                   0.5f * fmaf(v.z, v.z, v.w * v.w));
        }
    }
    __syncthreads();

    // ---- Phase A: argmin over candidate pairs (score = 0.5|q|^2 - p.q) ----
    u64 pxd[M], pyd[M];
    #pragma unroll
    for (int j = 0; j < M; j++) { pxd[j] = F2PK(px[j], px[j]); pyd[j] = F2PK(py[j], py[j]); }

    float sc[M]; int bp[M];     // best pair score / pair index
    #pragma unroll
    for (int j = 0; j < M; j++) { sc[j] = 3.4e38f; bp[j] = 0; }

    const ulonglong2* sCl64 = (const ulonglong2*)sCl;
    const u64* clh64 = (const u64*)sClh;
    #pragma unroll 8
    for (int it = 0; it < NCLP2 / 32; it++) {       // 32 iters
        int pi = l + it * 32;
        ulonglong2 uc = sCl64[pi];   // uc.x=(-qx0,-qx1), uc.y=(-qy0,-qy1)
        u64 h2 = clh64[pi];
        #pragma unroll
        for (int j = 0; j < M; j++) {
            u64 s2 = F2FMA(pxd[j], uc.x, F2FMA(pyd[j], uc.y, h2));
            float s0, s1; F2UP(s2, s0, s1);
            float pmin = fminf(s0, s1);
            if (pmin < sc[j]) { sc[j] = pmin; bp[j] = pi; }
        }
    }
    #pragma unroll
    for (int off = 16; off; off >>= 1) {
        #pragma unroll
        for (int j = 0; j < M; j++) {
            float os = __shfl_xor_sync(0xffffffffu, sc[j], off);
            int   oi = __shfl_xor_sync(0xffffffffu, bp[j], off);
            if (os < sc[j] || (os == sc[j] && oi < bp[j])) { sc[j] = os; bp[j] = oi; }
        }
    }
    // resolve which half of the winning pair (recompute one packed score)
    float dax[M], day[M];
    #pragma unroll
    for (int j = 0; j < M; j++) {
        ulonglong2 uc = sCl64[bp[j]];   // broadcast
        u64 h2 = clh64[bp[j]];
        u64 s2 = F2FMA(pxd[j], uc.x, F2FMA(pyd[j], uc.y, h2));
        float s0, s1; F2UP(s2, s0, s1);
        float nqx0, nqx1, nqy0, nqy1;
        F2UP(uc.x, nqx0, nqx1);
        F2UP(uc.y, nqy0, nqy1);
        bool h1 = (s1 < s0);            // tie -> half 0 (lower index)
        float nqx = h1 ? nqx1 : nqx0;
        float nqy = h1 ? nqy1 : nqy0;
        dax[j] = -nqx - px[j];          // qx - px
        day[j] = -nqy - py[j];
    }
    u64 px2[2]   = { F2PK(px[0], px[1]),   F2PK(px[2], px[3]) };
    u64 py2[2]   = { F2PK(py[0], py[1]),   F2PK(py[2], py[3]) };
    u64 dax2[2]  = { F2PK(dax[0], dax[1]), F2PK(dax[2], dax[3]) };
    u64 nday2[2] = { F2PK(-day[0], -day[1]), F2PK(-day[2], -day[3]) };
    const u64 neps2 = F2PK(-EPS_, -EPS_);

    // ---- Phase B: fused distance + intersection over segments ----
    float mind2[M];
    u64 hbits[2];
    #pragma unroll
    for (int j = 0; j < M; j++) mind2[j] = 3.4e38f;
    hbits[0] = 0ull; hbits[1] = 0ull;

    const ulonglong2* sA64 = (const ulonglong2*)sA;
    const ulonglong2* sD64 = (const ulonglong2*)sD;
    #pragma unroll 8
    for (int it = 0; it < NSEGP / 32; it++) {       // 32 iters
        int s = l + it * 32;
        ulonglong2 va = sA64[s];   // va.x=(-ax,-ax), va.y=(-ay,-ay)
        ulonglong2 vd = sD64[s];   // vd.x=(-dx,-dx), vd.y=(-dy,-dy)
        float ndxs, ndys, dum0, dum1;
        F2UP(vd.x, ndxs, dum0);
        F2UP(vd.y, ndys, dum1);
        float len2 = fmaf(ndxs, ndxs, fmaf(ndys, ndys, EPS_));
        float r = frcp(len2);
        #pragma unroll
        for (int q = 0; q < 2; q++) {
            int j0 = 2 * q, j1 = 2 * q + 1;
            u64 v1x = F2ADD(px2[q], va.x);          // p - a
            u64 v1y = F2ADD(py2[q], va.y);
            u64 ndt = F2FMA(v1y, vd.y, F2MUL(v1x, vd.x));   // -(v1.d)
            float n0, n1; F2UP(ndt, n0, n1);
            float p0 = __saturatef(-n0 * r);        // FMUL.SAT, neg folded
            float p1 = __saturatef(-n1 * r);
            u64 pr = F2PK(p0, p1);
            u64 ex = F2FMA(vd.x, pr, v1x);          // v1x - dx*pr
            u64 ey = F2FMA(vd.y, pr, v1y);
            u64 d2 = F2FMA(ey, ey, F2MUL(ex, ex));
            float d20, d21; F2UP(d2, d20, d21);
            mind2[j0] = fminf(mind2[j0], d20);
            mind2[j1] = fminf(mind2[j1], d21);
            // nw = -(cross(da,db)+eps); c1 = cross(da,v1); c2 = cross(db,v1)
            u64 nw = F2FMA(nday2[q], vd.x, F2FMA(dax2[q], vd.y, neps2));
            u64 c1 = F2FMA(dax2[q], v1y, F2MUL(nday2[q], v1x));
            u64 c2 = F2SUB(F2MUL(vd.y, v1x), F2MUL(vd.x, v1y));
            u64 s1 = F2MUL(c1, F2ADD(c1, nw));      // half-hit iff sign set
            u64 s2 = F2MUL(c2, F2ADD(c2, nw));
            hbits[q] |= (s1 & s2);                  // LOP3 sign-AND, OR-accumulate
        }
    }
    #pragma unroll
    for (int off = 16; off; off >>= 1) {
        #pragma unroll
        for (int j = 0; j < M; j++)
            mind2[j] = fminf(mind2[j], __shfl_xor_sync(0xffffffffu, mind2[j], off));
        #pragma unroll
        for (int q = 0; q < 2; q++)
            hbits[q] |= __shfl_xor_sync(0xffffffffu, hbits[q], off);
    }

    if (l == 0) {
        float acc = 0.0f;
        #pragma unroll
        for (int j = 0; j < M; j++) {
            u64 hb = hbits[j >> 1];
            unsigned hw = (j & 1) ? (unsigned)(hb >> 32) : (unsigned)hb;
            float md = sqrtf(mind2[j]);
            md = (hw & 0x80000000u) ? md : -md;   // sign set => intersect => outside
            acc += fmaxf(md + THRESH_, 0.0f);
        }
        sVal[w] = acc;
    }
    __syncthreads();

    // second-arriving block per (b,c) combines both halves into out.
    if (tid == 0) {
        float bsum = 0.0f;
        #pragma unroll
        for (int i = 0; i < WARPS; i++) bsum += sVal[i];
        g_scratch[idx * 2 + half] = bsum;
        __threadfence();
        unsigned old = atomicAdd(&g_tick[idx], 1u);
        if (old == 1u) {
            out[idx] = g_scratch[idx * 2] + g_scratch[idx * 2 + 1];
            g_tick[idx] = 0u;               // reset for next graph replay
        }
    }
}

extern "C" void kernel_launch(void* const* d_in, const int* in_sizes, int n_in,
                              void* d_out, int out_size) {
    const float* points      = (const float*)d_in[0];
    const float* road_bound  = (const float*)d_in[1];
    const float* centerlines = (const float*)d_in[2];
    float* out = (float*)d_out;
    (void)in_sizes; (void)n_in; (void)out_size;

    offroad_kernel<<<B_ * C_ * HALVES, THREADS>>>(points, road_bound, centerlines, out);
}

// round 17
// speedup vs baseline: 1.0111x; 1.0111x over previous
#include <cuda_runtime.h>
#include <cuda_bf16.h>
#include <math.h>

// Fixed shapes
#define B_ 32
#define C_ 6
#define T_ 64
#define K_ 8
#define N_ 128
#define NSEG 1016
#define NSEGP 1024
#define NCL 2048
#define NCLP2 1024             // candidate pairs
#define EPS_ 1e-6f
#define THRESH_ 0.5f
#define PAD_ 1e9f

#define THREADS 256
#define WARPS 8                // each warp = independent point group
#define M 4                    // points per warp
#define PTS_BLK (WARPS * M)    // 32
#define HALVES (T_ / PTS_BLK)  // 2
// grid = B*C*HALVES = 384

typedef unsigned long long u64;

__device__ float    g_scratch[B_ * C_ * 2];   // zero-init (.bss)
__device__ unsigned g_tick[B_ * C_];          // zero-init, reset after use

__device__ __forceinline__ u64 F2ADD(u64 a, u64 b) {
    u64 d; asm("add.rn.f32x2 %0,%1,%2;" : "=l"(d) : "l"(a), "l"(b)); return d;
}
__device__ __forceinline__ u64 F2SUB(u64 a, u64 b) {
    u64 d; asm("sub.rn.f32x2 %0,%1,%2;" : "=l"(d) : "l"(a), "l"(b)); return d;
}
__device__ __forceinline__ u64 F2MUL(u64 a, u64 b) {
    u64 d; asm("mul.rn.f32x2 %0,%1,%2;" : "=l"(d) : "l"(a), "l"(b)); return d;
}
__device__ __forceinline__ u64 F2FMA(u64 a, u64 b, u64 c) {
    u64 d; asm("fma.rn.f32x2 %0,%1,%2,%3;" : "=l"(d) : "l"(a), "l"(b), "l"(c)); return d;
}
__device__ __forceinline__ u64 F2PK(float lo, float hi) {
    u64 d; asm("mov.b64 %0,{%1,%2};" : "=l"(d) : "f"(lo), "f"(hi)); return d;
}
__device__ __forceinline__ void F2UP(u64 a, float& lo, float& hi) {
    asm("mov.b64 {%0,%1},%2;" : "=f"(lo), "=f"(hi) : "l"(a));
}
__device__ __forceinline__ float frcp(float x) {
    float r; asm("rcp.approx.f32 %0,%1;" : "=f"(r) : "f"(x)); return r;
}

__global__ __launch_bounds__(THREADS, 3)
void offroad_kernel(const float* __restrict__ points,
                    const float* __restrict__ road_boundary,
                    const float* __restrict__ centerlines,
                    float* __restrict__ out) {
    __shared__ float4 sA[NSEGP];     // (-ax,-ax,-ay,-ay)
    __shared__ float4 sD[NSEGP];     // (-dx,-dx,-dy,-dy)
    __shared__ float4 sCl[NCLP2];    // (-qx0,-qx1,-qy0,-qy1) per cand pair
    __shared__ float2 sClh[NCLP2];   // (h0,h1) = 0.5*|q|^2 per pair
    __shared__ float  sVal[WARPS];

    const int bid = blockIdx.x;
    const int half = bid & 1;
    const int c = (bid >> 1) % C_;
    const int b = bid / (2 * C_);
    const int idx = b * C_ + c;
    const int tid = threadIdx.x;

    const int w = tid >> 5;     // warp = point group (0..7)
    const int l = tid & 31;

    // ---- issue the points load FIRST (latency overlapped with prologue) ----
    float px[M], py[M];
    {
        const float2* pp = (const float2*)points +
            ((size_t)idx) * T_ + half * PTS_BLK + w * M;
        #pragma unroll
        for (int j = 0; j < M; j++) { float2 p = pp[j]; px[j] = p.x; py[j] = p.y; }
    }

    // ---- prologue: batch ALL global loads, then all stores ----
    {
        const float2* rb = (const float2*)road_boundary + (size_t)b * K_ * N_;
        const float4* cl4 = (const float4*)(centerlines + (size_t)b * NCL * 2);
        float2 aR[4], eR[4];
        float4 vR[4];
        #pragma unroll
        for (int i = 0; i < 4; i++) {
            int s = tid + i * THREADS;
            int ss = (s < NSEG) ? s : 0;
            int k = ss / (N_ - 1);
            int j = ss - k * (N_ - 1);
            aR[i] = rb[k * N_ + j];
            eR[i] = rb[k * N_ + j + 1];
        }
        #pragma unroll
        for (int i = 0; i < 4; i++) vR[i] = cl4[tid + i * THREADS];

        #pragma unroll
        for (int i = 0; i < 4; i++) {
            int s = tid + i * THREADS;
            float nax, nay, ndx, ndy;
            if (s < NSEG) {
                nax = -aR[i].x; nay = -aR[i].y;
                ndx = aR[i].x - eR[i].x; ndy = aR[i].y - eR[i].y;
            } else {
                nax = -PAD_; nay = -PAD_;   // a = (PAD, PAD), d = (1,0): inert
                ndx = -1.0f; ndy = 0.0f;
            }
            sA[s] = make_float4(nax, nax, nay, nay);
            sD[s] = make_float4(ndx, ndx, ndy, ndy);
        }
        #pragma unroll
        for (int i = 0; i < 4; i++) {
            int pi = tid + i * THREADS;
            float4 v = vR[i];   // (q0x,q0y,q1x,q1y)
            sCl[pi] = make_float4(-v.x, -v.z, -v.y, -v.w);
            sClh[pi] = make_float2(0.5f * fmaf(v.x, v.x, v.y * v.y),
                                   0.5f * fmaf(v.z, v.z, v.w * v.w));
        }
    }
    __syncthreads();

    // ---- Phase A: argmin over candidate pairs (score = 0.5|q|^2 - p.q) ----
    u64 pxd[M], pyd[M];
    #pragma unroll
    for (int j = 0; j < M; j++) { pxd[j] = F2PK(px[j], px[j]); pyd[j] = F2PK(py[j], py[j]); }

    float sc[M]; int bp[M];     // best pair score / pair index
    #pragma unroll
    for (int j = 0; j < M; j++) { sc[j] = 3.4e38f; bp[j] = 0; }

    const ulonglong2* sCl64 = (const ulonglong2*)sCl;
    const u64* clh64 = (const u64*)sClh;
    #pragma unroll 8
    for (int it = 0; it < NCLP2 / 32; it++) {       // 32 iters
        int pi = l + it * 32;
        ulonglong2 uc = sCl64[pi];   // uc.x=(-qx0,-qx1), uc.y=(-qy0,-qy1)
        u64 h2 = clh64[pi];
        #pragma unroll
        for (int j = 0; j < M; j++) {
            u64 s2 = F2FMA(pxd[j], uc.x, F2FMA(pyd[j], uc.y, h2));
            float s0, s1; F2UP(s2, s0, s1);
            float pmin = fminf(s0, s1);
            if (pmin < sc[j]) { sc[j] = pmin; bp[j] = pi; }
        }
    }
    #pragma unroll
    for (int off = 16; off; off >>= 1) {
        #pragma unroll
        for (int j = 0; j < M; j++) {
            float os = __shfl_xor_sync(0xffffffffu, sc[j], off);
            int   oi = __shfl_xor_sync(0xffffffffu, bp[j], off);
            if (os < sc[j] || (os == sc[j] && oi < bp[j])) { sc[j] = os; bp[j] = oi; }
        }
    }
    // resolve which half of the winning pair (recompute one packed score)
    float dax[M], day[M];
    #pragma unroll
    for (int j = 0; j < M; j++) {
        ulonglong2 uc = sCl64[bp[j]];   // broadcast
        u64 h2 = clh64[bp[j]];
        u64 s2 = F2FMA(pxd[j], uc.x, F2FMA(pyd[j], uc.y, h2));
        float s0, s1; F2UP(s2, s0, s1);
        float nqx0, nqx1, nqy0, nqy1;
        F2UP(uc.x, nqx0, nqx1);
        F2UP(uc.y, nqy0, nqy1);
        bool h1 = (s1 < s0);            // tie -> half 0 (lower index)
        float nqx = h1 ? nqx1 : nqx0;
        float nqy = h1 ? nqy1 : nqy0;
        dax[j] = -nqx - px[j];          // qx - px
        day[j] = -nqy - py[j];
    }
    u64 px2[2]   = { F2PK(px[0], px[1]),   F2PK(px[2], px[3]) };
    u64 py2[2]   = { F2PK(py[0], py[1]),   F2PK(py[2], py[3]) };
    u64 dax2[2]  = { F2PK(dax[0], dax[1]), F2PK(dax[2], dax[3]) };
    u64 nday2[2] = { F2PK(-day[0], -day[1]), F2PK(-day[2], -day[3]) };
    const u64 neps2 = F2PK(-EPS_, -EPS_);
    const u64 zero2 = 0ull;

    // ---- Phase B: fused distance + intersection over segments ----
    float mind2[M];
    u64 hbits[2];
    #pragma unroll
    for (int j = 0; j < M; j++) mind2[j] = 3.4e38f;
    hbits[0] = 0ull; hbits[1] = 0ull;

    const ulonglong2* sA64 = (const ulonglong2*)sA;
    const ulonglong2* sD64 = (const ulonglong2*)sD;
    #pragma unroll 8
    for (int it = 0; it < NSEGP / 32; it++) {       // 32 iters
        int s = l + it * 32;
        ulonglong2 va = sA64[s];   // va.x=(-ax,-ax), va.y=(-ay,-ay)
        ulonglong2 vd = sD64[s];   // vd.x=(-dx,-dx), vd.y=(-dy,-dy)
        float ndxs, ndys, dum0, dum1;
        F2UP(vd.x, ndxs, dum0);
        F2UP(vd.y, ndys, dum1);
        float len2 = fmaf(ndxs, ndxs, fmaf(ndys, ndys, EPS_));
        float r = frcp(len2);
        u64 dxp = F2SUB(zero2, vd.x);   // (dx,dx), hoisted once per segment
        #pragma unroll
        for (int q = 0; q < 2; q++) {
            int j0 = 2 * q, j1 = 2 * q + 1;
            u64 v1x = F2ADD(px2[q], va.x);          // p - a
            u64 v1y = F2ADD(py2[q], va.y);
            u64 ndt = F2FMA(v1y, vd.y, F2MUL(v1x, vd.x));   // -(v1.d)
            float n0, n1; F2UP(ndt, n0, n1);
            float p0 = __saturatef(-n0 * r);        // FMUL.SAT, neg folded
            float p1 = __saturatef(-n1 * r);
            u64 pr = F2PK(p0, p1);
            u64 ex = F2FMA(vd.x, pr, v1x);          // v1x - dx*pr
            u64 ey = F2FMA(vd.y, pr, v1y);
            u64 d2 = F2FMA(ey, ey, F2MUL(ex, ex));
            float d20, d21; F2UP(d2, d20, d21);
            mind2[j0] = fminf(mind2[j0], d20);
            mind2[j1] = fminf(mind2[j1], d21);
            // nw = -(cross(da,db)+eps); c1 = cross(da,v1); c2 = cross(db,v1)
            u64 nw = F2FMA(nday2[q], vd.x, F2FMA(dax2[q], vd.y, neps2));
            u64 c1 = F2FMA(dax2[q], v1y, F2MUL(nday2[q], v1x));
            u64 c2 = F2FMA(dxp,     v1y, F2MUL(vd.y,     v1x));   // dx*v1y - dy*v1x
            u64 s1 = F2MUL(c1, F2ADD(c1, nw));      // half-hit iff sign set
            u64 s2 = F2MUL(c2, F2ADD(c2, nw));
            hbits[q] |= (s1 & s2);                  // LOP3 sign-AND, OR-accumulate
        }
    }
    #pragma unroll
    for (int off = 16; off; off >>= 1) {
        #pragma unroll
        for (int j = 0; j < M; j++)
            mind2[j] = fminf(mind2[j], __shfl_xor_sync(0xffffffffu, mind2[j], off));
        #pragma unroll
        for (int q = 0; q < 2; q++)
            hbits[q] |= __shfl_xor_sync(0xffffffffu, hbits[q], off);
    }

    if (l == 0) {
        float acc = 0.0f;
        #pragma unroll
        for (int j = 0; j < M; j++) {
            u64 hb = hbits[j >> 1];
            unsigned hw = (j & 1) ? (unsigned)(hb >> 32) : (unsigned)hb;
            float md = sqrtf(mind2[j]);
            md = (hw & 0x80000000u) ? md : -md;   // sign set => intersect => outside
            acc += fmaxf(md + THRESH_, 0.0f);
        }
        sVal[w] = acc;
    }
    __syncthreads();

    // second-arriving block per (b,c) combines both halves into out.
    if (tid == 0) {
        float bsum = 0.0f;
        #pragma unroll
        for (int i = 0; i < WARPS; i++) bsum += sVal[i];
        g_scratch[idx * 2 + half] = bsum;
        __threadfence();
        unsigned old = atomicAdd(&g_tick[idx], 1u);
        if (old == 1u) {
            out[idx] = g_scratch[idx * 2] + g_scratch[idx * 2 + 1];
            g_tick[idx] = 0u;               // reset for next graph replay
        }
    }
}

extern "C" void kernel_launch(void* const* d_in, const int* in_sizes, int n_in,
                              void* d_out, int out_size) {
    const float* points      = (const float*)d_in[0];
    const float* road_bound  = (const float*)d_in[1];
    const float* centerlines = (const float*)d_in[2];
    float* out = (float*)d_out;
    (void)in_sizes; (void)n_in; (void)out_size;

    offroad_kernel<<<B_ * C_ * HALVES, THREADS>>>(points, road_bound, centerlines, out);
}